// round 5
// baseline (speedup 1.0000x reference)
#include <cuda_runtime.h>
#include <math.h>

// x: (256, 2048, 25, 2) fp32 -> 26,214,400 floats -> 6,553,600 float4.
// Only weights[0] is used. Joints 0..7 of each frame rotate by
// R=[[c,-s],[s,c]] applied as out = x @ R:
//   ox = x*c + y*s ; oy = -x*s + y*c.
//
// Each thread handles 4 consecutive float4 (= 8 (x,y) pairs, 64 bytes).
// All 4 loads are issued up front (MLP_p1 = 4) to hide DRAM latency.
// 6,553,600 / 4 = 1,638,400 threads = 6400 blocks x 256 (exact, no tail).

__global__ void __launch_bounds__(256)
rigid_rot_kernel4(const float4* __restrict__ xin,
                  const float*  __restrict__ w,
                  float4* __restrict__ out)
{
    unsigned t = blockIdx.x * 256u + threadIdx.x;
    unsigned base = t * 4u;                    // first float4 index

    // Front-batched loads: 4 independent LDG.128 in flight.
    float4 v0 = xin[base + 0u];
    float4 v1 = xin[base + 1u];
    float4 v2 = xin[base + 2u];
    float4 v3 = xin[base + 3u];

    float s, c;
    sincosf(__ldg(w), &s, &c);

    // joint index of the first pair handled by this thread
    unsigned j = (base * 2u) % 25u;            // one const-divisor mod

    #pragma unroll
    for (int k = 0; k < 4; ++k) {
        float4& v = (k == 0) ? v0 : (k == 1) ? v1 : (k == 2) ? v2 : v3;

        if (j < 8u) {
            float nx = fmaf(v.x, c, v.y * s);
            float ny = fmaf(v.y, c, -v.x * s);
            v.x = nx; v.y = ny;
        }
        j = (j + 1u == 25u) ? 0u : (j + 1u);

        if (j < 8u) {
            float nx = fmaf(v.z, c, v.w * s);
            float ny = fmaf(v.w, c, -v.z * s);
            v.z = nx; v.w = ny;
        }
        j = (j + 1u == 25u) ? 0u : (j + 1u);
    }

    out[base + 0u] = v0;
    out[base + 1u] = v1;
    out[base + 2u] = v2;
    out[base + 3u] = v3;
}

extern "C" void kernel_launch(void* const* d_in, const int* in_sizes, int n_in,
                              void* d_out, int out_size)
{
    const float4* x = (const float4*)d_in[0];
    const float*  w = (const float*)d_in[1];
    float4* out = (float4*)d_out;

    unsigned n4 = (unsigned)(out_size / 4);        // 6,553,600
    unsigned threads = n4 / 4u;                    // 1,638,400 (exact)
    unsigned blocks = threads / 256u;              // 6400 (exact)

    rigid_rot_kernel4<<<blocks, 256>>>(x, w, out);
}

// round 6
// speedup vs baseline: 1.1088x; 1.1088x over previous
#include <cuda_runtime.h>
#include <math.h>

// x: (256, 2048, 25, 2) fp32 -> 6,553,600 float4. Only weights[0] used.
// Joints 0..7 rotate by R=[[c,-s],[s,c]]: ox = x*c + y*s ; oy = -x*s + y*c.
//
// Grid-stride batching: each thread handles 4 float4s spaced S apart
// (S = total threads), so every LDG.128/STG.128 is perfectly coalesced
// across the warp while keeping 4 independent loads in flight (MLP=4).
// n4 = 6,553,600 = 4 * 1,638,400 ; 1,638,400 = 6400 blocks * 256 (exact).

__global__ void __launch_bounds__(256)
rigid_rot_gs4(const float4* __restrict__ xin,
              const float*  __restrict__ w,
              float4* __restrict__ out,
              unsigned S)                      // stride = total threads
{
    unsigned i = blockIdx.x * 256u + threadIdx.x;

    unsigned i0 = i;
    unsigned i1 = i + S;
    unsigned i2 = i + 2u * S;
    unsigned i3 = i + 3u * S;

    // Front-batched, fully coalesced streaming loads.
    float4 v0 = __ldcs(&xin[i0]);
    float4 v1 = __ldcs(&xin[i1]);
    float4 v2 = __ldcs(&xin[i2]);
    float4 v3 = __ldcs(&xin[i3]);

    float s, c;
    sincosf(__ldg(w), &s, &c);

    // Joint indices of the first pair in each segment.
    unsigned j0 = (2u * i0) % 25u;
    unsigned j1 = (2u * i1) % 25u;
    unsigned j2 = (2u * i2) % 25u;
    unsigned j3 = (2u * i3) % 25u;

    #pragma unroll
    for (int k = 0; k < 4; ++k) {
        float4& v = (k == 0) ? v0 : (k == 1) ? v1 : (k == 2) ? v2 : v3;
        unsigned j = (k == 0) ? j0 : (k == 1) ? j1 : (k == 2) ? j2 : j3;

        if (j < 8u) {
            float nx = fmaf(v.x, c, v.y * s);
            float ny = fmaf(v.y, c, -v.x * s);
            v.x = nx; v.y = ny;
        }
        unsigned jn = (j + 1u == 25u) ? 0u : (j + 1u);
        if (jn < 8u) {
            float nx = fmaf(v.z, c, v.w * s);
            float ny = fmaf(v.w, c, -v.z * s);
            v.z = nx; v.w = ny;
        }
    }

    __stcs(&out[i0], v0);
    __stcs(&out[i1], v1);
    __stcs(&out[i2], v2);
    __stcs(&out[i3], v3);
}

extern "C" void kernel_launch(void* const* d_in, const int* in_sizes, int n_in,
                              void* d_out, int out_size)
{
    const float4* x = (const float4*)d_in[0];
    const float*  w = (const float*)d_in[1];
    float4* out = (float4*)d_out;

    unsigned n4 = (unsigned)(out_size / 4);   // 6,553,600
    unsigned S  = n4 / 4u;                    // 1,638,400
    unsigned blocks = S / 256u;               // 6400

    rigid_rot_gs4<<<blocks, 256>>>(x, w, out, S);
}